// round 9
// baseline (speedup 1.0000x reference)
#include <cuda_runtime.h>
#include <cuda_bf16.h>
#include <math.h>
#include <stdint.h>

#define B_DIM 64
#define S_DIM 1000
#define K_DIM 12
#define N_DIM 80
#define NP 81
#define EPS 1e-5f
#define LOG_2PI 1.8378770664093453f

// ---- device scratch (no allocations allowed) ----
__device__ float g_cst[B_DIM * K_DIM];
__device__ float g_c[B_DIM * K_DIM * N_DIM];
// B operand pre-packed as m16n8k16 B-fragment image:
// idx = bk*1600 + ((kc*4+t)*80 + n);  .x = pack(W[kc*16+2t][n], W[kc*16+2t+1][n])
//                                     .y = pack(W[kc*16+2t+8][n], W[kc*16+2t+9][n])
__device__ uint2 g_wqhi[B_DIM * K_DIM * 1600];
__device__ uint2 g_wqlo[B_DIM * K_DIM * 1600];

__device__ __forceinline__ uint32_t pack_bf16(__nv_bfloat16 lo, __nv_bfloat16 hi) {
    return (uint32_t)__bfloat16_as_ushort(lo) | ((uint32_t)__bfloat16_as_ushort(hi) << 16);
}

__device__ __forceinline__ void mma16816(float d[4], const uint32_t a[4], uint32_t b0, uint32_t b1) {
    asm volatile(
        "mma.sync.aligned.m16n8k16.row.col.f32.bf16.bf16.f32 "
        "{%0,%1,%2,%3}, {%4,%5,%6,%7}, {%8,%9}, {%0,%1,%2,%3};"
        : "+f"(d[0]), "+f"(d[1]), "+f"(d[2]), "+f"(d[3])
        : "r"(a[0]), "r"(a[1]), "r"(a[2]), "r"(a[3]), "r"(b0), "r"(b1));
}

// ---------------------------------------------------------------------------
// Prep per (b,k): LDL^T -> Cholesky -> half-blocked L^{-1} -> W = L^{-T}, c,
// cst; emit W as bf16 hi/lo packed B-fragment images (g_wqhi/g_wqlo).
// ---------------------------------------------------------------------------
__global__ void __launch_bounds__(128) prep_kernel(const float* __restrict__ mu,
                                                   const float* __restrict__ sigma) {
    __shared__ float A[N_DIM * NP];
    __shared__ float Tb[40 * 41];
    __shared__ float rs[N_DIM];
    __shared__ float lg[N_DIM];

    int bk = blockIdx.x;
    int tid = threadIdx.x;

    const float* sig = sigma + (size_t)bk * N_DIM * N_DIM;
    for (int p = tid; p < N_DIM * N_DIM; p += 128) {
        int i = p / N_DIM, j = p % N_DIM;
        float v = sig[p];
        if (i == j) v += EPS;
        A[i * NP + j] = v;
    }

    // LDL^T: pivot j; one sync per pivot (invj computed redundantly per thread)
    for (int j = 0; j < N_DIM - 1; j++) {
        __syncthreads();
        float invj = 1.0f / A[j * NP + j];
        int c = j + 1 + tid;
        if (c < N_DIM) {
            float f = invj * A[c * NP + j];
            #pragma unroll 4
            for (int r = c; r < N_DIM; r++)
                A[r * NP + c] -= A[r * NP + j] * f;
        }
    }
    __syncthreads();

    if (tid < N_DIM) {
        float d = A[tid * NP + tid];
        rs[tid] = rsqrtf(d);
        lg[tid] = 0.5f * logf(d);
    }
    __syncthreads();

    for (int p = tid; p < N_DIM * N_DIM; p += 128) {
        int i = p / N_DIM, j = p % N_DIM;
        if (i >= j) A[i * NP + j] *= rs[j];
    }
    if (tid == 0) {
        float s = 0.f;
        for (int j = 0; j < N_DIM; j++) s += lg[j];
        g_cst[bk] = -s - 0.5f * N_DIM * LOG_2PI;
    }
    __syncthreads();

    // two independent 40x40 triangular inversions (one column per thread)
    if (tid < N_DIM) {
        int j = tid;
        int hi = (j < 40) ? 40 : 80;
        for (int i = j + 1; i < hi; i++) {
            float s = A[i * NP + j] * rs[j];
            for (int t = j + 1; t < i; t++)
                s += A[i * NP + t] * A[j * NP + t];
            A[j * NP + i] = -s * rs[i];
        }
    }
    __syncthreads();

    // Tb = L10 * M00
    for (int p = tid; p < 1600; p += 128) {
        int ii = p / 40, jj = p % 40;
        float s = A[(40 + ii) * NP + jj] * rs[jj];
        for (int t = jj + 1; t < 40; t++)
            s += A[(40 + ii) * NP + t] * A[jj * NP + t];
        Tb[ii * 41 + jj] = s;
    }
    __syncthreads();

    // M10 = -M11 * Tb
    for (int p = tid; p < 1600; p += 128) {
        int ii = p / 40, jj = p % 40;
        float s = rs[40 + ii] * Tb[ii * 41 + jj];
        for (int t = 0; t < ii; t++)
            s += A[(40 + t) * NP + (40 + ii)] * Tb[t * 41 + jj];
        A[jj * NP + (40 + ii)] = -s;
    }
    __syncthreads();

    // c = M * mu   (c_j = sum_{i<=j} mu_i * W[i][j], W[i][j]=M[j][i])
    const float* mub = mu + (size_t)bk * N_DIM;
    if (tid < N_DIM) {
        int j = tid;
        float c = mub[j] * rs[j];
        for (int i = 0; i < j; i++) c += mub[i] * A[i * NP + j];
        g_c[bk * N_DIM + j] = c;
    }
    __syncthreads();

    // Emit packed B fragments. W[k][n]: k<n -> A[k*NP+n]; k==n -> rs[k]; k>n -> 0
    uint2* wh = g_wqhi + (size_t)bk * 1600;
    uint2* wl = g_wqlo + (size_t)bk * 1600;
    for (int p = tid; p < 1600; p += 128) {
        int kc = p / 320;
        int t  = (p / 80) % 4;
        int n  = p % 80;
        int k0 = kc * 16 + 2 * t;
        float w[4];
        #pragma unroll
        for (int q = 0; q < 4; q++) {
            int k = k0 + ((q >= 2) ? 8 : 0) + (q & 1);
            float v = 0.f;
            if (k < n)       v = A[k * NP + n];
            else if (k == n) v = rs[k];
            w[q] = v;
        }
        __nv_bfloat16 h[4], l[4];
        #pragma unroll
        for (int q = 0; q < 4; q++) {
            h[q] = __float2bfloat16(w[q]);
            l[q] = __float2bfloat16(w[q] - __bfloat162float(h[q]));
        }
        wh[p] = make_uint2(pack_bf16(h[0], h[1]), pack_bf16(h[2], h[3]));
        wl[p] = make_uint2(pack_bf16(l[0], l[1]), pack_bf16(l[2], l[3]));
    }
}

// ---------------------------------------------------------------------------
// Main: mma.sync bf16 split-precision GEMM + fused epilogue.
// CTA: 256 thr (8 warps), tile = 128 s-rows of batch b; warp w owns rows
// [w*16, w*16+16) x FULL n=80. x converted f32->bf16 hi/lo during staging
// (2 passes through one smem buffer); A fragments resident in regs.
// Per state: stage B-fragment images, 10n x 5k x 3 mma, epilogue in-warp
// (subtract c, square, shfl-reduce over t, direct STG). One sync per state.
// ---------------------------------------------------------------------------
#define XP_STRIDE 44
#define WQ_STRIDE 84
#define SM_XP_WORDS (128 * XP_STRIDE)            // 5632 u32 = 22528 B
#define SM_WQ_BYTES (2 * 20 * WQ_STRIDE * 8)     // 26880 B
#define SM_TOTAL (SM_XP_WORDS * 4 + SM_WQ_BYTES) // 49408 B

__global__ void __launch_bounds__(256, 3) ll_mma_kernel(const float* __restrict__ x,
                                                        float* __restrict__ out) {
    extern __shared__ char smraw[];
    uint32_t* XP = (uint32_t*)smraw;                       // [128][44]
    uint2*    WQ = (uint2*)(smraw + SM_XP_WORDS * 4);      // [2][20][84]

    int tid = threadIdx.x;
    int wid = tid >> 5, lid = tid & 31;
    int g = lid >> 2, t = lid & 3;            // fragment row-group / col-pair
    int m0 = wid * 16;                        // warp's row base within tile
    int b = blockIdx.x, mt = blockIdx.y;
    int s0 = mt * 128;

    const float2* xb2 = (const float2*)(x + (size_t)b * S_DIM * N_DIM);

    // ---- stage x tile hi then lo through one buffer; A frags to regs
    uint32_t Ahi[5][4], Alo[5][4];
    #pragma unroll
    for (int pass = 0; pass < 2; pass++) {
        for (int p = tid; p < 128 * 40; p += 256) {
            int m = p / 40, k2 = p % 40;
            int srow = s0 + m;
            float2 v = make_float2(0.f, 0.f);
            if (srow < S_DIM) v = xb2[srow * 40 + k2];
            __nv_bfloat16 h0 = __float2bfloat16(v.x);
            __nv_bfloat16 h1 = __float2bfloat16(v.y);
            uint32_t w;
            if (pass == 0) {
                w = pack_bf16(h0, h1);
            } else {
                __nv_bfloat16 l0 = __float2bfloat16(v.x - __bfloat162float(h0));
                __nv_bfloat16 l1 = __float2bfloat16(v.y - __bfloat162float(h1));
                w = pack_bf16(l0, l1);
            }
            XP[m * XP_STRIDE + k2] = w;
        }
        __syncthreads();
        int r0 = (m0 + g) * XP_STRIDE;
        int r1 = (m0 + 8 + g) * XP_STRIDE;
        #pragma unroll
        for (int kc = 0; kc < 5; kc++) {
            int c0 = kc * 8 + t, c1 = kc * 8 + 4 + t;
            uint32_t* F = (pass == 0) ? Ahi[kc] : Alo[kc];
            F[0] = XP[r0 + c0];
            F[1] = XP[r1 + c0];
            F[2] = XP[r0 + c1];
            F[3] = XP[r1 + c1];
        }
        __syncthreads();
    }

    int srow_a = s0 + m0 + g;
    int srow_b = s0 + m0 + 8 + g;

    for (int k = 0; k < K_DIM; k++) {
        int bk = b * K_DIM + k;

        // ---- stage B fragment images for this state
        {
            const uint2* wh = g_wqhi + (size_t)bk * 1600;
            const uint2* wl = g_wqlo + (size_t)bk * 1600;
            for (int p = tid; p < 1600; p += 256) {
                int row = p / 80, n = p % 80;
                WQ[row * WQ_STRIDE + n]                  = wh[p];
                WQ[20 * WQ_STRIDE + row * WQ_STRIDE + n] = wl[p];
            }
        }
        __syncthreads();

        float qa = 0.f, qb = 0.f;
        const float* cbase = g_c + bk * N_DIM;
        #pragma unroll
        for (int j = 0; j < 10; j++) {
            float d[4] = {0.f, 0.f, 0.f, 0.f};
            int n = j * 8 + g;
            #pragma unroll
            for (int kc = 0; kc < 5; kc++) {
                uint2 bh = WQ[(kc * 4 + t) * WQ_STRIDE + n];
                uint2 bl = WQ[20 * WQ_STRIDE + (kc * 4 + t) * WQ_STRIDE + n];
                mma16816(d, Ahi[kc], bh.x, bh.y);
                mma16816(d, Alo[kc], bh.x, bh.y);
                mma16816(d, Ahi[kc], bl.x, bl.y);
            }
            int col = j * 8 + 2 * t;
            float2 cc = *(const float2*)(cbase + col);
            float e0 = d[0] - cc.x, e1 = d[1] - cc.y;
            float e2 = d[2] - cc.x, e3 = d[3] - cc.y;
            qa = fmaf(e0, e0, qa); qa = fmaf(e1, e1, qa);
            qb = fmaf(e2, e2, qb); qb = fmaf(e3, e3, qb);
        }
        // reduce over t (4 lanes per fragment row)
        qa += __shfl_xor_sync(0xffffffffu, qa, 1);
        qa += __shfl_xor_sync(0xffffffffu, qa, 2);
        qb += __shfl_xor_sync(0xffffffffu, qb, 1);
        qb += __shfl_xor_sync(0xffffffffu, qb, 2);
        if (t == 0) {
            float cst = g_cst[bk];
            if (srow_a < S_DIM)
                out[((size_t)b * S_DIM + srow_a) * K_DIM + k] = fmaf(-0.5f, qa, cst);
            if (srow_b < S_DIM)
                out[((size_t)b * S_DIM + srow_b) * K_DIM + k] = fmaf(-0.5f, qb, cst);
        }
        __syncthreads();   // WQ free for next state
    }
}

// ---------------------------------------------------------------------------
extern "C" void kernel_launch(void* const* d_in, const int* in_sizes, int n_in,
                              void* d_out, int out_size) {
    const float* x     = (const float*)d_in[0];
    const float* mu    = (const float*)d_in[1];
    const float* sigma = (const float*)d_in[2];
    float* out = (float*)d_out;

    prep_kernel<<<B_DIM * K_DIM, 128>>>(mu, sigma);

    cudaFuncSetAttribute(ll_mma_kernel, cudaFuncAttributeMaxDynamicSharedMemorySize, SM_TOTAL);
    ll_mma_kernel<<<dim3(B_DIM, 8), 256, SM_TOTAL>>>(x, out);
}

// round 10
// speedup vs baseline: 1.2471x; 1.2471x over previous
#include <cuda_runtime.h>
#include <cuda_bf16.h>
#include <math.h>
#include <stdint.h>

#define B_DIM 64
#define S_DIM 1000
#define K_DIM 12
#define N_DIM 80
#define NP 81
#define EPS 1e-5f
#define LOG_2PI 1.8378770664093453f
#define SUBT 63                       // ceil(1000/16) m-subtiles

// ---- device scratch (no allocations allowed) ----
__device__ float g_cst[B_DIM * K_DIM];
__device__ float g_c[B_DIM * K_DIM * N_DIM];
// B operand packed as m16n8k16 B-fragment image:
// idx = bk*1600 + ((kc*4+t)*80 + n);  .x = pack(W[kc*16+2t][n], W[kc*16+2t+1][n])
//                                     .y = pack(W[kc*16+2t+8][n], W[kc*16+2t+9][n])
__device__ uint2 g_wqhi[B_DIM * K_DIM * 1600];
__device__ uint2 g_wqlo[B_DIM * K_DIM * 1600];
// A operand packed as m16n8k16 A-fragment image (uint4 = 4 frag regs per lane/kc):
// idx = ((b*SUBT + ms)*5 + kc)*32 + lane
__device__ uint4 g_afhi[B_DIM * SUBT * 5 * 32];
__device__ uint4 g_aflo[B_DIM * SUBT * 5 * 32];

__device__ __forceinline__ uint32_t pack_bf16(__nv_bfloat16 lo, __nv_bfloat16 hi) {
    return (uint32_t)__bfloat16_as_ushort(lo) | ((uint32_t)__bfloat16_as_ushort(hi) << 16);
}
__device__ __forceinline__ uint32_t hi_pack(float a, float b) {
    return pack_bf16(__float2bfloat16(a), __float2bfloat16(b));
}
__device__ __forceinline__ uint32_t lo_pack(float a, float b) {
    __nv_bfloat16 ha = __float2bfloat16(a), hb = __float2bfloat16(b);
    return pack_bf16(__float2bfloat16(a - __bfloat162float(ha)),
                     __float2bfloat16(b - __bfloat162float(hb)));
}

__device__ __forceinline__ void mma16816(float d[4], const uint32_t a[4], uint32_t b0, uint32_t b1) {
    asm volatile(
        "mma.sync.aligned.m16n8k16.row.col.f32.bf16.bf16.f32 "
        "{%0,%1,%2,%3}, {%4,%5,%6,%7}, {%8,%9}, {%0,%1,%2,%3};"
        : "+f"(d[0]), "+f"(d[1]), "+f"(d[2]), "+f"(d[3])
        : "r"(a[0]), "r"(a[1]), "r"(a[2]), "r"(a[3]), "r"(b0), "r"(b1));
}

// ---------------------------------------------------------------------------
// convert_x: build the A-fragment image. One thread per (b, ms, kc, lane):
// 4 float2 loads -> hi uint4 + lo uint4, coalesced uint4 stores.
// ---------------------------------------------------------------------------
__global__ void __launch_bounds__(256) convert_x(const float* __restrict__ x) {
    int idx = blockIdx.x * 256 + threadIdx.x;
    if (idx >= B_DIM * SUBT * 5 * 32) return;
    int lane = idx & 31;
    int rest = idx >> 5;
    int kc = rest % 5;  rest /= 5;
    int ms = rest % SUBT;
    int b  = rest / SUBT;
    int g = lane >> 2, t = lane & 3;
    int sa = ms * 16 + g, sb = sa + 8;
    int w0 = kc * 8 + t, w1 = w0 + 4;
    const float2* xb = (const float2*)(x + (size_t)b * S_DIM * N_DIM);
    float2 z = make_float2(0.f, 0.f);
    float2 a0 = (sa < S_DIM) ? xb[sa * 40 + w0] : z;
    float2 b0 = (sb < S_DIM) ? xb[sb * 40 + w0] : z;
    float2 a1 = (sa < S_DIM) ? xb[sa * 40 + w1] : z;
    float2 b1 = (sb < S_DIM) ? xb[sb * 40 + w1] : z;
    g_afhi[idx] = make_uint4(hi_pack(a0.x, a0.y), hi_pack(b0.x, b0.y),
                             hi_pack(a1.x, a1.y), hi_pack(b1.x, b1.y));
    g_aflo[idx] = make_uint4(lo_pack(a0.x, a0.y), lo_pack(b0.x, b0.y),
                             lo_pack(a1.x, a1.y), lo_pack(b1.x, b1.y));
}

// ---------------------------------------------------------------------------
// Prep: ONE WARP per (b,k). LDL^T (syncwarp-only pivots) -> Cholesky ->
// half-blocked L^{-1} -> c, cst, W emitted as packed B-fragment images.
// ---------------------------------------------------------------------------
__global__ void __launch_bounds__(32) prep_kernel(const float* __restrict__ mu,
                                                  const float* __restrict__ sigma) {
    __shared__ float A[N_DIM * NP];     // 25.9 KB
    __shared__ float Tb[40 * 41];       // 6.6 KB
    __shared__ float rs[N_DIM];
    __shared__ float lg[N_DIM];

    int bk = blockIdx.x;
    int lane = threadIdx.x;

    // load sigma (+ eps I) via float4 (80 % 4 == 0 -> quad stays in one row)
    const float4* s4 = (const float4*)(sigma + (size_t)bk * N_DIM * N_DIM);
    for (int p4 = lane; p4 < 1600; p4 += 32) {
        float4 v = s4[p4];
        int p = p4 * 4;
        int i = p / N_DIM, j = p % N_DIM;
        A[i * NP + j]     = v.x + (i == j     ? EPS : 0.f);
        A[i * NP + j + 1] = v.y + (i == j + 1 ? EPS : 0.f);
        A[i * NP + j + 2] = v.z + (i == j + 2 ? EPS : 0.f);
        A[i * NP + j + 3] = v.w + (i == j + 3 ? EPS : 0.f);
    }
    __syncwarp();

    // LDL^T: pivot j; lane updates trailing columns c = j+1+lane (+32, +64)
    for (int j = 0; j < N_DIM - 1; j++) {
        float invj = 1.0f / A[j * NP + j];
        for (int c = j + 1 + lane; c < N_DIM; c += 32) {
            float f = invj * A[c * NP + j];
            #pragma unroll 4
            for (int r = c; r < N_DIM; r++)
                A[r * NP + c] -= A[r * NP + j] * f;
        }
        __syncwarp();
    }

    // diag -> rs, lg
    for (int i = lane; i < N_DIM; i += 32) {
        float d = A[i * NP + i];
        rs[i] = rsqrtf(d);
        lg[i] = 0.5f * logf(d);
    }
    __syncwarp();

    // normalize to Cholesky L
    for (int p = lane; p < N_DIM * N_DIM; p += 32) {
        int i = p / N_DIM, j = p % N_DIM;
        if (i >= j) A[i * NP + j] *= rs[j];
    }
    // logdet via warp reduce
    {
        float s = lg[lane] + lg[lane + 32] + ((lane + 64 < N_DIM) ? lg[lane + 64] : 0.f);
        #pragma unroll
        for (int o = 16; o > 0; o >>= 1) s += __shfl_xor_sync(0xffffffffu, s, o);
        if (lane == 0) g_cst[bk] = -s - 0.5f * N_DIM * LOG_2PI;
    }
    __syncwarp();

    // two independent 40x40 triangular inversions, columns j, j+32, j+64 per lane
    // M[i][j] (i>j) stored at A[j*NP+i]; diag M = rs
    for (int j = lane; j < N_DIM; j += 32) {
        int hi = (j < 40) ? 40 : 80;
        for (int i = j + 1; i < hi; i++) {
            float s = A[i * NP + j] * rs[j];
            for (int t = j + 1; t < i; t++)
                s += A[i * NP + t] * A[j * NP + t];
            A[j * NP + i] = -s * rs[i];
        }
    }
    __syncwarp();

    // Tb = L10 * M00
    for (int p = lane; p < 1600; p += 32) {
        int ii = p / 40, jj = p % 40;
        float s = A[(40 + ii) * NP + jj] * rs[jj];
        for (int t = jj + 1; t < 40; t++)
            s += A[(40 + ii) * NP + t] * A[jj * NP + t];
        Tb[ii * 41 + jj] = s;
    }
    __syncwarp();

    // M10 = -M11 * Tb
    for (int p = lane; p < 1600; p += 32) {
        int ii = p / 40, jj = p % 40;
        float s = rs[40 + ii] * Tb[ii * 41 + jj];
        for (int t = 0; t < ii; t++)
            s += A[(40 + t) * NP + (40 + ii)] * Tb[t * 41 + jj];
        A[jj * NP + (40 + ii)] = -s;
    }
    __syncwarp();

    // c = M * mu
    const float* mub = mu + (size_t)bk * N_DIM;
    for (int j = lane; j < N_DIM; j += 32) {
        float c = mub[j] * rs[j];
        for (int i = 0; i < j; i++) c += mub[i] * A[i * NP + j];
        g_c[bk * N_DIM + j] = c;
    }
    __syncwarp();

    // Emit packed B fragments. W[k][n]: k<n -> A[k*NP+n]; k==n -> rs[k]; else 0
    uint2* wh = g_wqhi + (size_t)bk * 1600;
    uint2* wl = g_wqlo + (size_t)bk * 1600;
    for (int p = lane; p < 1600; p += 32) {
        int kc = p / 320;
        int t  = (p / 80) % 4;
        int n  = p % 80;
        int k0 = kc * 16 + 2 * t;
        float w[4];
        #pragma unroll
        for (int q = 0; q < 4; q++) {
            int k = k0 + ((q >= 2) ? 8 : 0) + (q & 1);
            float v = 0.f;
            if (k < n)       v = A[k * NP + n];
            else if (k == n) v = rs[k];
            w[q] = v;
        }
        wh[p] = make_uint2(hi_pack(w[0], w[1]), hi_pack(w[2], w[3]));
        wl[p] = make_uint2(lo_pack(w[0], w[1]), lo_pack(w[2], w[3]));
    }
}

// ---------------------------------------------------------------------------
// Main: CTA per (b,k). B-fragment image staged to smem ONCE; c-fragments and
// cst in registers; ONE __syncthreads. 4 warps sweep 63 m-subtiles (ms = wid
// mod 4); per subtile: 10 coalesced LDG.128 A-frags, 150 mma, in-warp epilogue.
// ---------------------------------------------------------------------------
#define WQ_STRIDE 84

__global__ void __launch_bounds__(128, 4) ll_mma_kernel(float* __restrict__ out) {
    __shared__ uint2 WQ[2 * 20 * WQ_STRIDE];   // 26880 B

    int tid = threadIdx.x;
    int wid = tid >> 5, lid = tid & 31;
    int g = lid >> 2, t = lid & 3;
    int k = blockIdx.x, b = blockIdx.y;
    int bk = b * K_DIM + k;

    // stage B fragments (once)
    {
        const uint2* wh = g_wqhi + (size_t)bk * 1600;
        const uint2* wl = g_wqlo + (size_t)bk * 1600;
        for (int p = tid; p < 1600; p += 128) {
            int row = p / 80, n = p % 80;
            WQ[row * WQ_STRIDE + n]                       = wh[p];
            WQ[20 * WQ_STRIDE + row * WQ_STRIDE + n]      = wl[p];
        }
    }
    // c fragments + cst to registers
    float2 cc[10];
    {
        const float* cbase = g_c + bk * N_DIM;
        #pragma unroll
        for (int j = 0; j < 10; j++)
            cc[j] = *(const float2*)(cbase + j * 8 + 2 * t);
    }
    float cst = g_cst[bk];
    __syncthreads();

    const uint4* afh = g_afhi + ((size_t)b * SUBT) * 5 * 32 + lid;
    const uint4* afl = g_aflo + ((size_t)b * SUBT) * 5 * 32 + lid;

    for (int ms = wid; ms < SUBT; ms += 4) {
        // load A fragments (coalesced LDG.128)
        uint4 AH[5], AL[5];
        const uint4* ah = afh + (size_t)ms * 5 * 32;
        const uint4* al = afl + (size_t)ms * 5 * 32;
        #pragma unroll
        for (int kc = 0; kc < 5; kc++) {
            AH[kc] = ah[kc * 32];
            AL[kc] = al[kc * 32];
        }

        float qa = 0.f, qb = 0.f;
        #pragma unroll
        for (int j = 0; j < 10; j++) {
            float d[4] = {0.f, 0.f, 0.f, 0.f};
            int n = j * 8 + g;
            #pragma unroll
            for (int kc = 0; kc < 5; kc++) {
                uint2 bh = WQ[(kc * 4 + t) * WQ_STRIDE + n];
                uint2 bl = WQ[20 * WQ_STRIDE + (kc * 4 + t) * WQ_STRIDE + n];
                mma16816(d, (const uint32_t*)&AH[kc], bh.x, bh.y);
                mma16816(d, (const uint32_t*)&AL[kc], bh.x, bh.y);
                mma16816(d, (const uint32_t*)&AH[kc], bl.x, bl.y);
            }
            float e0 = d[0] - cc[j].x, e1 = d[1] - cc[j].y;
            float e2 = d[2] - cc[j].x, e3 = d[3] - cc[j].y;
            qa = fmaf(e0, e0, qa); qa = fmaf(e1, e1, qa);
            qb = fmaf(e2, e2, qb); qb = fmaf(e3, e3, qb);
        }
        qa += __shfl_xor_sync(0xffffffffu, qa, 1);
        qa += __shfl_xor_sync(0xffffffffu, qa, 2);
        qb += __shfl_xor_sync(0xffffffffu, qb, 1);
        qb += __shfl_xor_sync(0xffffffffu, qb, 2);
        if (t == 0) {
            int sa = ms * 16 + g, sb = sa + 8;
            if (sa < S_DIM)
                out[((size_t)b * S_DIM + sa) * K_DIM + k] = fmaf(-0.5f, qa, cst);
            if (sb < S_DIM)
                out[((size_t)b * S_DIM + sb) * K_DIM + k] = fmaf(-0.5f, qb, cst);
        }
    }
}

// ---------------------------------------------------------------------------
extern "C" void kernel_launch(void* const* d_in, const int* in_sizes, int n_in,
                              void* d_out, int out_size) {
    const float* x     = (const float*)d_in[0];
    const float* mu    = (const float*)d_in[1];
    const float* sigma = (const float*)d_in[2];
    float* out = (float*)d_out;

    convert_x<<<(B_DIM * SUBT * 5 * 32 + 255) / 256, 256>>>(x);
    prep_kernel<<<B_DIM * K_DIM, 32>>>(mu, sigma);
    ll_mma_kernel<<<dim3(K_DIM, B_DIM), 128>>>(out);
}

// round 11
// speedup vs baseline: 1.6623x; 1.3330x over previous
#include <cuda_runtime.h>
#include <cuda_bf16.h>
#include <math.h>
#include <stdint.h>

#define B_DIM 64
#define S_DIM 1000
#define K_DIM 12
#define N_DIM 80
#define NP 81
#define EPS 1e-5f
#define LOG_2PI 1.8378770664093453f
#define SUBT 63                       // ceil(1000/16) m-subtiles

// ---- device scratch (no allocations allowed) ----
__device__ float g_cst[B_DIM * K_DIM];
__device__ float g_c[B_DIM * K_DIM * N_DIM];
// B operand packed as m16n8k16 B-fragment image:
// idx = bk*1600 + ((kc*4+t)*80 + n);  .x = pack(W[kc*16+2t][n], W[kc*16+2t+1][n])
//                                     .y = pack(W[kc*16+2t+8][n], W[kc*16+2t+9][n])
__device__ uint2 g_wqhi[B_DIM * K_DIM * 1600];
__device__ uint2 g_wqlo[B_DIM * K_DIM * 1600];
// A operand packed as m16n8k16 A-fragment image (uint4 = 4 frag regs per lane/kc):
// idx = ((b*SUBT + ms)*5 + kc)*32 + lane
__device__ uint4 g_afhi[B_DIM * SUBT * 5 * 32];
__device__ uint4 g_aflo[B_DIM * SUBT * 5 * 32];

__device__ __forceinline__ uint32_t pack_bf16(__nv_bfloat16 lo, __nv_bfloat16 hi) {
    return (uint32_t)__bfloat16_as_ushort(lo) | ((uint32_t)__bfloat16_as_ushort(hi) << 16);
}
__device__ __forceinline__ uint32_t hi_pack(float a, float b) {
    return pack_bf16(__float2bfloat16(a), __float2bfloat16(b));
}
__device__ __forceinline__ uint32_t lo_pack(float a, float b) {
    __nv_bfloat16 ha = __float2bfloat16(a), hb = __float2bfloat16(b);
    return pack_bf16(__float2bfloat16(a - __bfloat162float(ha)),
                     __float2bfloat16(b - __bfloat162float(hb)));
}

__device__ __forceinline__ void mma16816(float d[4], const uint32_t a[4], uint32_t b0, uint32_t b1) {
    asm volatile(
        "mma.sync.aligned.m16n8k16.row.col.f32.bf16.bf16.f32 "
        "{%0,%1,%2,%3}, {%4,%5,%6,%7}, {%8,%9}, {%0,%1,%2,%3};"
        : "+f"(d[0]), "+f"(d[1]), "+f"(d[2]), "+f"(d[3])
        : "r"(a[0]), "r"(a[1]), "r"(a[2]), "r"(a[3]), "r"(b0), "r"(b1));
}

// ---------------------------------------------------------------------------
// convert_x: build the A-fragment image. One thread per (b, ms, kc, lane):
// 4 float2 loads -> hi uint4 + lo uint4, coalesced uint4 stores.
// ---------------------------------------------------------------------------
__global__ void __launch_bounds__(256) convert_x(const float* __restrict__ x) {
    int idx = blockIdx.x * 256 + threadIdx.x;
    if (idx >= B_DIM * SUBT * 5 * 32) return;
    int lane = idx & 31;
    int rest = idx >> 5;
    int kc = rest % 5;  rest /= 5;
    int ms = rest % SUBT;
    int b  = rest / SUBT;
    int g = lane >> 2, t = lane & 3;
    int sa = ms * 16 + g, sb = sa + 8;
    int w0 = kc * 8 + t, w1 = w0 + 4;
    const float2* xb = (const float2*)(x + (size_t)b * S_DIM * N_DIM);
    float2 z = make_float2(0.f, 0.f);
    float2 a0 = (sa < S_DIM) ? xb[sa * 40 + w0] : z;
    float2 b0 = (sb < S_DIM) ? xb[sb * 40 + w0] : z;
    float2 a1 = (sa < S_DIM) ? xb[sa * 40 + w1] : z;
    float2 b1 = (sb < S_DIM) ? xb[sb * 40 + w1] : z;
    g_afhi[idx] = make_uint4(hi_pack(a0.x, a0.y), hi_pack(b0.x, b0.y),
                             hi_pack(a1.x, a1.y), hi_pack(b1.x, b1.y));
    g_aflo[idx] = make_uint4(lo_pack(a0.x, a0.y), lo_pack(b0.x, b0.y),
                             lo_pack(a1.x, a1.y), lo_pack(b1.x, b1.y));
}

// ---------------------------------------------------------------------------
// Prep per (b,k), 128 threads. Key fix vs prior rounds: the pivot column is
// copied to a SEPARATE smem array (colj) each step, so the trailing update
// reads only colj (alias-free) and its A accesses differ by compile-time
// constant NP between iterations -> ptxas pipelines the loop instead of
// serializing on unprovable store->load aliasing (~35 cyc/elem -> ~1).
// ---------------------------------------------------------------------------
__global__ void __launch_bounds__(128) prep_kernel(const float* __restrict__ mu,
                                                   const float* __restrict__ sigma) {
    __shared__ float A[N_DIM * NP];     // 25.9 KB
    __shared__ float colj[N_DIM];
    __shared__ float Tb[40 * 41];       // 6.6 KB
    __shared__ float rs[N_DIM];
    __shared__ float lg[N_DIM];

    int bk = blockIdx.x;
    int tid = threadIdx.x;

    const float* sig = sigma + (size_t)bk * N_DIM * N_DIM;
    for (int p = tid; p < N_DIM * N_DIM; p += 128) {
        int i = p / N_DIM, j = p % N_DIM;
        float v = sig[p];
        if (i == j) v += EPS;
        A[i * NP + j] = v;
    }

    // ---- LDL^T (unnormalized): pivot j; thread owns trailing column c
    for (int j = 0; j < N_DIM - 1; j++) {
        __syncthreads();                       // prior step's updates done
        for (int r = j + tid; r < N_DIM; r += 128) colj[r] = A[r * NP + j];
        __syncthreads();                       // colj ready
        float invj = 1.0f / colj[j];
        int c = j + 1 + tid;
        if (c < N_DIM) {
            float f = invj * colj[c];
            #pragma unroll 4
            for (int r = c; r < N_DIM; r++)
                A[r * NP + c] -= colj[r] * f;  // alias-free: colj separate, A stride NP
        }
    }
    __syncthreads();

    // ---- diag -> rs, lg
    if (tid < N_DIM) {
        float d = A[tid * NP + tid];
        rs[tid] = rsqrtf(d);
        lg[tid] = 0.5f * logf(d);
    }
    __syncthreads();

    // ---- normalize to Cholesky L
    for (int p = tid; p < N_DIM * N_DIM; p += 128) {
        int i = p / N_DIM, j = p % N_DIM;
        if (i >= j) A[i * NP + j] *= rs[j];
    }
    if (tid == 0) {
        float s = 0.f;
        for (int j = 0; j < N_DIM; j++) s += lg[j];
        g_cst[bk] = -s - 0.5f * N_DIM * LOG_2PI;
    }
    __syncthreads();

    // ---- two independent 40x40 triangular inversions (one column per thread)
    // M[i][j] (i>j) stored at A[j*NP+i]; diag M = rs
    if (tid < N_DIM) {
        int j = tid;
        int hi = (j < 40) ? 40 : 80;
        for (int i = j + 1; i < hi; i++) {
            float s = A[i * NP + j] * rs[j];
            for (int t = j + 1; t < i; t++)
                s += A[i * NP + t] * A[j * NP + t];
            A[j * NP + i] = -s * rs[i];
        }
    }
    __syncthreads();

    // ---- Tb = L10 * M00
    for (int p = tid; p < 1600; p += 128) {
        int ii = p / 40, jj = p % 40;
        float s = A[(40 + ii) * NP + jj] * rs[jj];
        for (int t = jj + 1; t < 40; t++)
            s += A[(40 + ii) * NP + t] * A[jj * NP + t];
        Tb[ii * 41 + jj] = s;
    }
    __syncthreads();

    // ---- M10 = -M11 * Tb
    for (int p = tid; p < 1600; p += 128) {
        int ii = p / 40, jj = p % 40;
        float s = rs[40 + ii] * Tb[ii * 41 + jj];
        for (int t = 0; t < ii; t++)
            s += A[(40 + t) * NP + (40 + ii)] * Tb[t * 41 + jj];
        A[jj * NP + (40 + ii)] = -s;
    }
    __syncthreads();

    // ---- c = M * mu
    const float* mub = mu + (size_t)bk * N_DIM;
    if (tid < N_DIM) {
        int j = tid;
        float c = mub[j] * rs[j];
        for (int i = 0; i < j; i++) c += mub[i] * A[i * NP + j];
        g_c[bk * N_DIM + j] = c;
    }
    __syncthreads();

    // ---- Emit packed B fragments. W[k][n]: k<n -> A[k*NP+n]; k==n -> rs[k]; else 0
    uint2* wh = g_wqhi + (size_t)bk * 1600;
    uint2* wl = g_wqlo + (size_t)bk * 1600;
    for (int p = tid; p < 1600; p += 128) {
        int kc = p / 320;
        int t  = (p / 80) % 4;
        int n  = p % 80;
        int k0 = kc * 16 + 2 * t;
        float w[4];
        #pragma unroll
        for (int q = 0; q < 4; q++) {
            int k = k0 + ((q >= 2) ? 8 : 0) + (q & 1);
            float v = 0.f;
            if (k < n)       v = A[k * NP + n];
            else if (k == n) v = rs[k];
            w[q] = v;
        }
        wh[p] = make_uint2(hi_pack(w[0], w[1]), hi_pack(w[2], w[3]));
        wl[p] = make_uint2(lo_pack(w[0], w[1]), lo_pack(w[2], w[3]));
    }
}

// ---------------------------------------------------------------------------
// Main: CTA per (b,k), 256 threads (8 warps). B-fragment image staged to smem
// ONCE; c-fragments and cst in registers; ONE __syncthreads. Warps sweep the
// 63 m-subtiles stride-8; per subtile: 10 coalesced LDG.128 A-frags, 150 mma,
// in-warp epilogue (subtract c, square, shfl-reduce over t, direct STG).
// ---------------------------------------------------------------------------
#define WQ_STRIDE 84

__global__ void __launch_bounds__(256) ll_mma_kernel(float* __restrict__ out) {
    __shared__ uint2 WQ[2 * 20 * WQ_STRIDE];   // 26880 B

    int tid = threadIdx.x;
    int wid = tid >> 5, lid = tid & 31;
    int g = lid >> 2, t = lid & 3;
    int k = blockIdx.x, b = blockIdx.y;
    int bk = b * K_DIM + k;

    // stage B fragments (once)
    {
        const uint2* wh = g_wqhi + (size_t)bk * 1600;
        const uint2* wl = g_wqlo + (size_t)bk * 1600;
        for (int p = tid; p < 1600; p += 256) {
            int row = p / 80, n = p % 80;
            WQ[row * WQ_STRIDE + n]                  = wh[p];
            WQ[20 * WQ_STRIDE + row * WQ_STRIDE + n] = wl[p];
        }
    }
    // c fragments + cst to registers
    float2 cc[10];
    {
        const float* cbase = g_c + bk * N_DIM;
        #pragma unroll
        for (int j = 0; j < 10; j++)
            cc[j] = *(const float2*)(cbase + j * 8 + 2 * t);
    }
    float cst = g_cst[bk];
    __syncthreads();

    const uint4* afh = g_afhi + ((size_t)b * SUBT) * 5 * 32 + lid;
    const uint4* afl = g_aflo + ((size_t)b * SUBT) * 5 * 32 + lid;

    for (int ms = wid; ms < SUBT; ms += 8) {
        // load A fragments (coalesced LDG.128, L2-resident)
        uint4 AH[5], AL[5];
        const uint4* ah = afh + (size_t)ms * 5 * 32;
        const uint4* al = afl + (size_t)ms * 5 * 32;
        #pragma unroll
        for (int kc = 0; kc < 5; kc++) {
            AH[kc] = ah[kc * 32];
            AL[kc] = al[kc * 32];
        }

        float qa = 0.f, qb = 0.f;
        #pragma unroll
        for (int j = 0; j < 10; j++) {
            float d[4] = {0.f, 0.f, 0.f, 0.f};
            int n = j * 8 + g;
            #pragma unroll
            for (int kc = 0; kc < 5; kc++) {
                uint2 bh = WQ[(kc * 4 + t) * WQ_STRIDE + n];
                uint2 bl = WQ[20 * WQ_STRIDE + (kc * 4 + t) * WQ_STRIDE + n];
                mma16816(d, (const uint32_t*)&AH[kc], bh.x, bh.y);
                mma16816(d, (const uint32_t*)&AL[kc], bh.x, bh.y);
                mma16816(d, (const uint32_t*)&AH[kc], bl.x, bl.y);
            }
            float e0 = d[0] - cc[j].x, e1 = d[1] - cc[j].y;
            float e2 = d[2] - cc[j].x, e3 = d[3] - cc[j].y;
            qa = fmaf(e0, e0, qa); qa = fmaf(e1, e1, qa);
            qb = fmaf(e2, e2, qb); qb = fmaf(e3, e3, qb);
        }
        qa += __shfl_xor_sync(0xffffffffu, qa, 1);
        qa += __shfl_xor_sync(0xffffffffu, qa, 2);
        qb += __shfl_xor_sync(0xffffffffu, qb, 1);
        qb += __shfl_xor_sync(0xffffffffu, qb, 2);
        if (t == 0) {
            int sa = ms * 16 + g, sb = sa + 8;
            if (sa < S_DIM)
                out[((size_t)b * S_DIM + sa) * K_DIM + k] = fmaf(-0.5f, qa, cst);
            if (sb < S_DIM)
                out[((size_t)b * S_DIM + sb) * K_DIM + k] = fmaf(-0.5f, qb, cst);
        }
    }
}

// ---------------------------------------------------------------------------
extern "C" void kernel_launch(void* const* d_in, const int* in_sizes, int n_in,
                              void* d_out, int out_size) {
    const float* x     = (const float*)d_in[0];
    const float* mu    = (const float*)d_in[1];
    const float* sigma = (const float*)d_in[2];
    float* out = (float*)d_out;

    convert_x<<<(B_DIM * SUBT * 5 * 32 + 255) / 256, 256>>>(x);
    prep_kernel<<<B_DIM * K_DIM, 128>>>(mu, sigma);
    ll_mma_kernel<<<dim3(K_DIM, B_DIM), 256>>>(out);
}

// round 12
// speedup vs baseline: 1.8935x; 1.1391x over previous
#include <cuda_runtime.h>
#include <cuda_bf16.h>
#include <math.h>
#include <stdint.h>

#define B_DIM 64
#define S_DIM 1000
#define K_DIM 12
#define N_DIM 80
#define NP 81
#define EPS 1e-5f
#define LOG_2PI 1.8378770664093453f
#define SUBT 63                       // ceil(1000/16) m-subtiles

// ---- device scratch (no allocations allowed) ----
__device__ float g_cst[B_DIM * K_DIM];
__device__ float g_c[B_DIM * K_DIM * N_DIM];
// B operand packed as m16n8k16 B-fragment image:
// idx = bk*1600 + ((kc*4+t)*80 + n);  .x = pack(W[kc*16+2t][n], W[kc*16+2t+1][n])
//                                     .y = pack(W[kc*16+2t+8][n], W[kc*16+2t+9][n])
__device__ uint2 g_wqhi[B_DIM * K_DIM * 1600];
__device__ uint2 g_wqlo[B_DIM * K_DIM * 1600];
// A operand packed as m16n8k16 A-fragment image (uint4 = 4 frag regs per lane/kc):
// idx = ((b*SUBT + ms)*5 + kc)*32 + lane
__device__ uint4 g_afhi[B_DIM * SUBT * 5 * 32];
__device__ uint4 g_aflo[B_DIM * SUBT * 5 * 32];

__device__ __forceinline__ uint32_t pack_bf16(__nv_bfloat16 lo, __nv_bfloat16 hi) {
    return (uint32_t)__bfloat16_as_ushort(lo) | ((uint32_t)__bfloat16_as_ushort(hi) << 16);
}
__device__ __forceinline__ uint32_t hi_pack(float a, float b) {
    return pack_bf16(__float2bfloat16(a), __float2bfloat16(b));
}
__device__ __forceinline__ uint32_t lo_pack(float a, float b) {
    __nv_bfloat16 ha = __float2bfloat16(a), hb = __float2bfloat16(b);
    return pack_bf16(__float2bfloat16(a - __bfloat162float(ha)),
                     __float2bfloat16(b - __bfloat162float(hb)));
}

__device__ __forceinline__ void mma16816(float d[4], const uint32_t a[4], uint32_t b0, uint32_t b1) {
    asm volatile(
        "mma.sync.aligned.m16n8k16.row.col.f32.bf16.bf16.f32 "
        "{%0,%1,%2,%3}, {%4,%5,%6,%7}, {%8,%9}, {%0,%1,%2,%3};"
        : "+f"(d[0]), "+f"(d[1]), "+f"(d[2]), "+f"(d[3])
        : "r"(a[0]), "r"(a[1]), "r"(a[2]), "r"(a[3]), "r"(b0), "r"(b1));
}

// ---------------------------------------------------------------------------
// convert_x: build the A-fragment image. One thread per (b, ms, kc, lane):
// 4 float2 loads -> hi uint4 + lo uint4, coalesced uint4 stores.
// ---------------------------------------------------------------------------
__global__ void __launch_bounds__(256) convert_x(const float* __restrict__ x) {
    int idx = blockIdx.x * 256 + threadIdx.x;
    if (idx >= B_DIM * SUBT * 5 * 32) return;
    int lane = idx & 31;
    int rest = idx >> 5;
    int kc = rest % 5;  rest /= 5;
    int ms = rest % SUBT;
    int b  = rest / SUBT;
    int g = lane >> 2, t = lane & 3;
    int sa = ms * 16 + g, sb = sa + 8;
    int w0 = kc * 8 + t, w1 = w0 + 4;
    const float2* xb = (const float2*)(x + (size_t)b * S_DIM * N_DIM);
    float2 z = make_float2(0.f, 0.f);
    float2 a0 = (sa < S_DIM) ? xb[sa * 40 + w0] : z;
    float2 b0 = (sb < S_DIM) ? xb[sb * 40 + w0] : z;
    float2 a1 = (sa < S_DIM) ? xb[sa * 40 + w1] : z;
    float2 b1 = (sb < S_DIM) ? xb[sb * 40 + w1] : z;
    g_afhi[idx] = make_uint4(hi_pack(a0.x, a0.y), hi_pack(b0.x, b0.y),
                             hi_pack(a1.x, a1.y), hi_pack(b1.x, b1.y));
    g_aflo[idx] = make_uint4(lo_pack(a0.x, a0.y), lo_pack(b0.x, b0.y),
                             lo_pack(a1.x, a1.y), lo_pack(b1.x, b1.y));
}

// ---------------------------------------------------------------------------
// Prep per (b,k), 128 threads. Pivot column copied to separate smem (colj)
// each step -> alias-free trailing update that ptxas can pipeline.
// ---------------------------------------------------------------------------
__global__ void __launch_bounds__(128) prep_kernel(const float* __restrict__ mu,
                                                   const float* __restrict__ sigma) {
    __shared__ float A[N_DIM * NP];     // 25.9 KB
    __shared__ float colj[N_DIM];
    __shared__ float Tb[40 * 41];       // 6.6 KB
    __shared__ float rs[N_DIM];
    __shared__ float lg[N_DIM];

    int bk = blockIdx.x;
    int tid = threadIdx.x;

    const float* sig = sigma + (size_t)bk * N_DIM * N_DIM;
    for (int p = tid; p < N_DIM * N_DIM; p += 128) {
        int i = p / N_DIM, j = p % N_DIM;
        float v = sig[p];
        if (i == j) v += EPS;
        A[i * NP + j] = v;
    }

    // ---- LDL^T (unnormalized): pivot j; thread owns trailing column c
    for (int j = 0; j < N_DIM - 1; j++) {
        __syncthreads();                       // prior step's updates done
        for (int r = j + tid; r < N_DIM; r += 128) colj[r] = A[r * NP + j];
        __syncthreads();                       // colj ready
        float invj = 1.0f / colj[j];
        int c = j + 1 + tid;
        if (c < N_DIM) {
            float f = invj * colj[c];
            #pragma unroll 4
            for (int r = c; r < N_DIM; r++)
                A[r * NP + c] -= colj[r] * f;  // alias-free: colj separate, A stride NP
        }
    }
    __syncthreads();

    // ---- diag -> rs, lg
    if (tid < N_DIM) {
        float d = A[tid * NP + tid];
        rs[tid] = rsqrtf(d);
        lg[tid] = 0.5f * logf(d);
    }
    __syncthreads();

    // ---- normalize to Cholesky L
    for (int p = tid; p < N_DIM * N_DIM; p += 128) {
        int i = p / N_DIM, j = p % N_DIM;
        if (i >= j) A[i * NP + j] *= rs[j];
    }
    if (tid == 0) {
        float s = 0.f;
        for (int j = 0; j < N_DIM; j++) s += lg[j];
        g_cst[bk] = -s - 0.5f * N_DIM * LOG_2PI;
    }
    __syncthreads();

    // ---- two independent 40x40 triangular inversions (one column per thread)
    // M[i][j] (i>j) stored at A[j*NP+i]; diag M = rs
    if (tid < N_DIM) {
        int j = tid;
        int hi = (j < 40) ? 40 : 80;
        for (int i = j + 1; i < hi; i++) {
            float s = A[i * NP + j] * rs[j];
            for (int t = j + 1; t < i; t++)
                s += A[i * NP + t] * A[j * NP + t];
            A[j * NP + i] = -s * rs[i];
        }
    }
    __syncthreads();

    // ---- Tb = L10 * M00
    for (int p = tid; p < 1600; p += 128) {
        int ii = p / 40, jj = p % 40;
        float s = A[(40 + ii) * NP + jj] * rs[jj];
        for (int t = jj + 1; t < 40; t++)
            s += A[(40 + ii) * NP + t] * A[jj * NP + t];
        Tb[ii * 41 + jj] = s;
    }
    __syncthreads();

    // ---- M10 = -M11 * Tb
    for (int p = tid; p < 1600; p += 128) {
        int ii = p / 40, jj = p % 40;
        float s = rs[40 + ii] * Tb[ii * 41 + jj];
        for (int t = 0; t < ii; t++)
            s += A[(40 + t) * NP + (40 + ii)] * Tb[t * 41 + jj];
        A[jj * NP + (40 + ii)] = -s;
    }
    __syncthreads();

    // ---- c = M * mu
    const float* mub = mu + (size_t)bk * N_DIM;
    if (tid < N_DIM) {
        int j = tid;
        float c = mub[j] * rs[j];
        for (int i = 0; i < j; i++) c += mub[i] * A[i * NP + j];
        g_c[bk * N_DIM + j] = c;
    }
    __syncthreads();

    // ---- Emit packed B fragments. W[k][n]: k<n -> A[k*NP+n]; k==n -> rs[k]; else 0
    uint2* wh = g_wqhi + (size_t)bk * 1600;
    uint2* wl = g_wqlo + (size_t)bk * 1600;
    for (int p = tid; p < 1600; p += 128) {
        int kc = p / 320;
        int t  = (p / 80) % 4;
        int n  = p % 80;
        int k0 = kc * 16 + 2 * t;
        float w[4];
        #pragma unroll
        for (int q = 0; q < 4; q++) {
            int k = k0 + ((q >= 2) ? 8 : 0) + (q & 1);
            float v = 0.f;
            if (k < n)       v = A[k * NP + n];
            else if (k == n) v = rs[k];
            w[q] = v;
        }
        wh[p] = make_uint2(hi_pack(w[0], w[1]), hi_pack(w[2], w[3]));
        wl[p] = make_uint2(lo_pack(w[0], w[1]), lo_pack(w[2], w[3]));
    }
}

// ---------------------------------------------------------------------------
// Main: CTA per (b,k), 256 threads (8 warps). B-fragment image staged ONCE;
// c/cst in registers; ONE __syncthreads. Warps sweep 63 m-subtiles stride-8.
// TRIANGULAR SKIP: for n-block j only kc <= j/2 contribute (W upper-tri), so
// j-pairs (2jp, 2jp+1) share kcmax=jp -> 90 mma/subtile (vs 150) and two
// independent accumulator chains per pair (2x tensor-pipe ILP).
// ---------------------------------------------------------------------------
#define WQ_STRIDE 84

__global__ void __launch_bounds__(256) ll_mma_kernel(float* __restrict__ out) {
    __shared__ uint2 WQ[2 * 20 * WQ_STRIDE];   // 26880 B

    int tid = threadIdx.x;
    int wid = tid >> 5, lid = tid & 31;
    int g = lid >> 2, t = lid & 3;
    int k = blockIdx.x, b = blockIdx.y;
    int bk = b * K_DIM + k;

    // stage B fragments (once)
    {
        const uint2* wh = g_wqhi + (size_t)bk * 1600;
        const uint2* wl = g_wqlo + (size_t)bk * 1600;
        for (int p = tid; p < 1600; p += 256) {
            int row = p / 80, n = p % 80;
            WQ[row * WQ_STRIDE + n]                  = wh[p];
            WQ[20 * WQ_STRIDE + row * WQ_STRIDE + n] = wl[p];
        }
    }
    // c fragments + cst to registers
    float2 cc[10];
    {
        const float* cbase = g_c + bk * N_DIM;
        #pragma unroll
        for (int j = 0; j < 10; j++)
            cc[j] = *(const float2*)(cbase + j * 8 + 2 * t);
    }
    float cst = g_cst[bk];
    __syncthreads();

    const uint4* afh = g_afhi + ((size_t)b * SUBT) * 5 * 32 + lid;
    const uint4* afl = g_aflo + ((size_t)b * SUBT) * 5 * 32 + lid;

    for (int ms = wid; ms < SUBT; ms += 8) {
        // load A fragments (coalesced LDG.128, L2-resident)
        uint4 AH[5], AL[5];
        const uint4* ah = afh + (size_t)ms * 5 * 32;
        const uint4* al = afl + (size_t)ms * 5 * 32;
        #pragma unroll
        for (int kc = 0; kc < 5; kc++) {
            AH[kc] = ah[kc * 32];
            AL[kc] = al[kc * 32];
        }

        float qa = 0.f, qb = 0.f;
        #pragma unroll
        for (int jp = 0; jp < 5; jp++) {
            float d0[4] = {0.f, 0.f, 0.f, 0.f};
            float d1[4] = {0.f, 0.f, 0.f, 0.f};
            int n0 = jp * 16 + g;
            int n1 = n0 + 8;
            #pragma unroll
            for (int kc = 0; kc <= jp; kc++) {     // triangular: kc <= j/2
                int row = (kc * 4 + t) * WQ_STRIDE;
                uint2 bh0 = WQ[row + n0];
                uint2 bh1 = WQ[row + n1];
                uint2 bl0 = WQ[20 * WQ_STRIDE + row + n0];
                uint2 bl1 = WQ[20 * WQ_STRIDE + row + n1];
                const uint32_t* ah32 = (const uint32_t*)&AH[kc];
                const uint32_t* al32 = (const uint32_t*)&AL[kc];
                mma16816(d0, ah32, bh0.x, bh0.y);
                mma16816(d1, ah32, bh1.x, bh1.y);
                mma16816(d0, al32, bh0.x, bh0.y);
                mma16816(d1, al32, bh1.x, bh1.y);
                mma16816(d0, ah32, bl0.x, bl0.y);
                mma16816(d1, ah32, bl1.x, bl1.y);
            }
            float2 c0 = cc[2 * jp], c1 = cc[2 * jp + 1];
            float e;
            e = d0[0] - c0.x; qa = fmaf(e, e, qa);
            e = d0[1] - c0.y; qa = fmaf(e, e, qa);
            e = d0[2] - c0.x; qb = fmaf(e, e, qb);
            e = d0[3] - c0.y; qb = fmaf(e, e, qb);
            e = d1[0] - c1.x; qa = fmaf(e, e, qa);
            e = d1[1] - c1.y; qa = fmaf(e, e, qa);
            e = d1[2] - c1.x; qb = fmaf(e, e, qb);
            e = d1[3] - c1.y; qb = fmaf(e, e, qb);
        }
        qa += __shfl_xor_sync(0xffffffffu, qa, 1);
        qa += __shfl_xor_sync(0xffffffffu, qa, 2);
        qb += __shfl_xor_sync(0xffffffffu, qb, 1);
        qb += __shfl_xor_sync(0xffffffffu, qb, 2);
        if (t == 0) {
            int sa = ms * 16 + g, sb = sa + 8;
            if (sa < S_DIM)
                out[((size_t)b * S_DIM + sa) * K_DIM + k] = fmaf(-0.5f, qa, cst);
            if (sb < S_DIM)
                out[((size_t)b * S_DIM + sb) * K_DIM + k] = fmaf(-0.5f, qb, cst);
        }
    }
}

// ---------------------------------------------------------------------------
extern "C" void kernel_launch(void* const* d_in, const int* in_sizes, int n_in,
                              void* d_out, int out_size) {
    const float* x     = (const float*)d_in[0];
    const float* mu    = (const float*)d_in[1];
    const float* sigma = (const float*)d_in[2];
    float* out = (float*)d_out;

    convert_x<<<(B_DIM * SUBT * 5 * 32 + 255) / 256, 256>>>(x);
    prep_kernel<<<B_DIM * K_DIM, 128>>>(mu, sigma);
    ll_mma_kernel<<<dim3(K_DIM, B_DIM), 256>>>(out);
}